// round 1
// baseline (speedup 1.0000x reference)
#include <cuda_runtime.h>
#include <math.h>

#define BB 4
#define TT 2048
#define CC 1024
#define HH 16
#define DD 64

// Scratch (static device allocations are the allowed workaround)
__device__ float g_q[(size_t)BB * HH * DD * TT];   // [b][h][d][t]  (transposed for attention)
__device__ float g_k[(size_t)BB * HH * DD * TT];   // [b][h][d][t]  (transposed for attention)
__device__ float g_v[(size_t)BB * HH * TT * DD];   // [b][h][t][d]
__device__ float g_attn[(size_t)BB * TT * CC];     // [b][t][h*DD+d] (concat-heads layout)

// ---------------------------------------------------------------------------
// Kernel 1: fused QKV projection.  C[m][n] = sum_k x[m][k] * W[n][k]
// m = b*T + t (8192), n = h*DD + d (1024).  blockIdx.z selects q/k/v.
// q,k written transposed [b][h][d][t]; v written [b][h][t][d].
// ---------------------------------------------------------------------------
__global__ __launch_bounds__(256) void qkv_kernel(
    const float* __restrict__ x, const float* __restrict__ Wq,
    const float* __restrict__ Wk, const float* __restrict__ Wv)
{
    const int z = blockIdx.z;
    const float* __restrict__ W = (z == 0) ? Wq : ((z == 1) ? Wk : Wv);

    __shared__ __align__(16) float At[32][68];
    __shared__ __align__(16) float Bt[32][68];

    const int tid = threadIdx.x;
    const int tx = tid & 15, ty = tid >> 4;
    const int m0 = blockIdx.y * 64;
    const int n0 = blockIdx.x * 64;

    float acc[4][4] = {};

    for (int k0 = 0; k0 < CC; k0 += 32) {
        #pragma unroll
        for (int r = 0; r < 2; r++) {
            int idx = (tid + r * 256) * 4;    // 0..2047, tile = 64 rows x 32 k
            int row = idx >> 5;
            int kk  = idx & 31;
            float4 a = *(const float4*)(x + (size_t)(m0 + row) * CC + k0 + kk);
            At[kk + 0][row] = a.x; At[kk + 1][row] = a.y;
            At[kk + 2][row] = a.z; At[kk + 3][row] = a.w;
            float4 b = *(const float4*)(W + (size_t)(n0 + row) * CC + k0 + kk);
            Bt[kk + 0][row] = b.x; Bt[kk + 1][row] = b.y;
            Bt[kk + 2][row] = b.z; Bt[kk + 3][row] = b.w;
        }
        __syncthreads();
        #pragma unroll
        for (int kk = 0; kk < 32; kk++) {
            float4 a4 = *(const float4*)&At[kk][ty * 4];
            float4 b4 = *(const float4*)&Bt[kk][tx * 4];
            float av[4] = {a4.x, a4.y, a4.z, a4.w};
            float bv[4] = {b4.x, b4.y, b4.z, b4.w};
            #pragma unroll
            for (int i = 0; i < 4; i++)
                #pragma unroll
                for (int j = 0; j < 4; j++)
                    acc[i][j] += av[i] * bv[j];
        }
        __syncthreads();
    }

    const int b  = m0 >> 11;            // 2048 rows per batch, tile never straddles
    const int t0 = m0 & (TT - 1);
    const int h  = n0 >> 6;             // tile spans exactly one head
    const size_t bh = (size_t)(b * HH + h);

    if (z < 2) {
        float* __restrict__ out = (z == 0) ? g_q : g_k;   // [bh][d][t]
        #pragma unroll
        for (int i = 0; i < 4; i++) {
            int t = t0 + ty * 4 + i;
            #pragma unroll
            for (int j = 0; j < 4; j++) {
                int d = tx * 4 + j;
                out[(bh * DD + d) * TT + t] = acc[i][j];
            }
        }
    } else {
        #pragma unroll
        for (int i = 0; i < 4; i++) {
            int t = t0 + ty * 4 + i;
            float4 v4 = make_float4(acc[i][0], acc[i][1], acc[i][2], acc[i][3]);
            *(float4*)&g_v[(bh * TT + t) * DD + tx * 4] = v4;
        }
    }
}

// ---------------------------------------------------------------------------
// Kernel 2: causal flash attention, fp32.
// grid.x = q-tile (32), grid.y = b*H + h (64).  64x64 tiles, online softmax.
// Score scale (x8, reproducing the reference's sqrt(HS) multiply) folded into Q.
// ---------------------------------------------------------------------------
#define SROW 68   // padded smem row stride (floats); 68*4 B, 16B-aligned rows

__global__ __launch_bounds__(256, 2) void attn_kernel()
{
    extern __shared__ __align__(16) float sm[];
    float* Qt = sm;                 // [64 d][64 q]
    float* Kt = sm + 64 * SROW;     // [64 d][64 key]
    float* Vs = sm + 2 * 64 * SROW; // [64 key][64 d]
    float* Ps = sm + 3 * 64 * SROW; // [64 q][64 key]

    const int tid = threadIdx.x;
    const int tx = tid & 15, ty = tid >> 4;
    const int qt = blockIdx.x;
    const int bh = blockIdx.y;
    const int q0 = qt * 64;

    const float* __restrict__ Qg = g_q + (size_t)bh * DD * TT; // [d][t]
    const float* __restrict__ Kg = g_k + (size_t)bh * DD * TT; // [d][t]
    const float* __restrict__ Vg = g_v + (size_t)bh * TT * DD; // [t][d]

    // Load Q tile once, scaled by 8 (the reference's *sqrt(64) bug)
    #pragma unroll
    for (int r = 0; r < 4; r++) {
        int idx = (tid + r * 256) * 4;     // 0..4095
        int d  = idx >> 6;
        int ql = idx & 63;
        float4 q4 = *(const float4*)(Qg + (size_t)d * TT + q0 + ql);
        *(float4*)&Qt[d * SROW + ql] =
            make_float4(q4.x * 8.f, q4.y * 8.f, q4.z * 8.f, q4.w * 8.f);
    }

    float oacc[4][4] = {};
    float mrow[4] = {-INFINITY, -INFINITY, -INFINITY, -INFINITY};
    float lrow[4] = {0.f, 0.f, 0.f, 0.f};

    const int ntiles = qt + 1;   // causal: only key tiles <= q tile
    for (int kt = 0; kt < ntiles; kt++) {
        const int kb = kt * 64;

        #pragma unroll
        for (int r = 0; r < 4; r++) {
            int idx = (tid + r * 256) * 4;
            int row = idx >> 6;
            int col = idx & 63;
            float4 k4 = *(const float4*)(Kg + (size_t)row * TT + kb + col);
            *(float4*)&Kt[row * SROW + col] = k4;
            float4 v4 = *(const float4*)(Vg + (size_t)(kb + row) * DD + col);
            *(float4*)&Vs[row * SROW + col] = v4;
        }
        __syncthreads();

        // S = Q . K^T  (64x64, d-major operands)
        float acc[4][4] = {};
        #pragma unroll 16
        for (int d = 0; d < 64; d++) {
            float4 qa = *(const float4*)&Qt[d * SROW + ty * 4];
            float4 ka = *(const float4*)&Kt[d * SROW + tx * 4];
            float qv[4] = {qa.x, qa.y, qa.z, qa.w};
            float kv[4] = {ka.x, ka.y, ka.z, ka.w};
            #pragma unroll
            for (int i = 0; i < 4; i++)
                #pragma unroll
                for (int j = 0; j < 4; j++)
                    acc[i][j] += qv[i] * kv[j];
        }

        if (kt == qt) {  // diagonal tile: causal mask
            #pragma unroll
            for (int i = 0; i < 4; i++)
                #pragma unroll
                for (int j = 0; j < 4; j++)
                    if (tx * 4 + j > ty * 4 + i) acc[i][j] = -INFINITY;
        }

        // Online softmax + write P to smem
        #pragma unroll
        for (int i = 0; i < 4; i++) {
            float mx = fmaxf(fmaxf(acc[i][0], acc[i][1]), fmaxf(acc[i][2], acc[i][3]));
            #pragma unroll
            for (int o = 8; o >= 1; o >>= 1)
                mx = fmaxf(mx, __shfl_xor_sync(0xffffffffu, mx, o));
            float mnew  = fmaxf(mrow[i], mx);
            float alpha = __expf(mrow[i] - mnew);
            float p[4], psum = 0.f;
            #pragma unroll
            for (int j = 0; j < 4; j++) { p[j] = __expf(acc[i][j] - mnew); psum += p[j]; }
            #pragma unroll
            for (int o = 8; o >= 1; o >>= 1)
                psum += __shfl_xor_sync(0xffffffffu, psum, o);
            lrow[i] = lrow[i] * alpha + psum;
            mrow[i] = mnew;
            #pragma unroll
            for (int j = 0; j < 4; j++) oacc[i][j] *= alpha;
            *(float4*)&Ps[(ty * 4 + i) * SROW + tx * 4] = make_float4(p[0], p[1], p[2], p[3]);
        }
        __syncthreads();

        // O += P . V  (k-dim = key)
        #pragma unroll 16
        for (int kk = 0; kk < 64; kk++) {
            float4 va = *(const float4*)&Vs[kk * SROW + tx * 4];
            float vv[4] = {va.x, va.y, va.z, va.w};
            float pv[4];
            #pragma unroll
            for (int i = 0; i < 4; i++) pv[i] = Ps[(ty * 4 + i) * SROW + kk];
            #pragma unroll
            for (int i = 0; i < 4; i++)
                #pragma unroll
                for (int j = 0; j < 4; j++)
                    oacc[i][j] += pv[i] * vv[j];
        }
        __syncthreads();
    }

    const int b = bh >> 4;
    const int h = bh & 15;
    #pragma unroll
    for (int i = 0; i < 4; i++) {
        int t = q0 + ty * 4 + i;
        float inv = 1.f / lrow[i];
        float4 o4 = make_float4(oacc[i][0] * inv, oacc[i][1] * inv,
                                oacc[i][2] * inv, oacc[i][3] * inv);
        *(float4*)&g_attn[((size_t)b * TT + t) * CC + h * DD + tx * 4] = o4;
    }
}

// ---------------------------------------------------------------------------
// Kernel 3: output projection.  out[m][n] = sum_k attn[m][k]*Wo[n][k] + bo[n]
// ---------------------------------------------------------------------------
__global__ __launch_bounds__(256) void proj_kernel(
    const float* __restrict__ Wo, const float* __restrict__ bo,
    float* __restrict__ out)
{
    __shared__ __align__(16) float At[32][68];
    __shared__ __align__(16) float Bt[32][68];

    const int tid = threadIdx.x;
    const int tx = tid & 15, ty = tid >> 4;
    const int m0 = blockIdx.y * 64;
    const int n0 = blockIdx.x * 64;

    float acc[4][4] = {};

    for (int k0 = 0; k0 < CC; k0 += 32) {
        #pragma unroll
        for (int r = 0; r < 2; r++) {
            int idx = (tid + r * 256) * 4;
            int row = idx >> 5;
            int kk  = idx & 31;
            float4 a = *(const float4*)(g_attn + (size_t)(m0 + row) * CC + k0 + kk);
            At[kk + 0][row] = a.x; At[kk + 1][row] = a.y;
            At[kk + 2][row] = a.z; At[kk + 3][row] = a.w;
            float4 b = *(const float4*)(Wo + (size_t)(n0 + row) * CC + k0 + kk);
            Bt[kk + 0][row] = b.x; Bt[kk + 1][row] = b.y;
            Bt[kk + 2][row] = b.z; Bt[kk + 3][row] = b.w;
        }
        __syncthreads();
        #pragma unroll
        for (int kk = 0; kk < 32; kk++) {
            float4 a4 = *(const float4*)&At[kk][ty * 4];
            float4 b4 = *(const float4*)&Bt[kk][tx * 4];
            float av[4] = {a4.x, a4.y, a4.z, a4.w};
            float bv[4] = {b4.x, b4.y, b4.z, b4.w};
            #pragma unroll
            for (int i = 0; i < 4; i++)
                #pragma unroll
                for (int j = 0; j < 4; j++)
                    acc[i][j] += av[i] * bv[j];
        }
        __syncthreads();
    }

    float4 b4 = *(const float4*)(bo + n0 + tx * 4);
    float bb[4] = {b4.x, b4.y, b4.z, b4.w};
    #pragma unroll
    for (int i = 0; i < 4; i++) {
        int m = m0 + ty * 4 + i;
        float4 o4 = make_float4(acc[i][0] + bb[0], acc[i][1] + bb[1],
                                acc[i][2] + bb[2], acc[i][3] + bb[3]);
        *(float4*)&out[(size_t)m * CC + n0 + tx * 4] = o4;
    }
}

// ---------------------------------------------------------------------------
extern "C" void kernel_launch(void* const* d_in, const int* in_sizes, int n_in,
                              void* d_out, int out_size)
{
    const float* x  = (const float*)d_in[0];
    const float* Wq = (const float*)d_in[1];
    const float* Wk = (const float*)d_in[2];
    const float* Wv = (const float*)d_in[3];
    const float* Wo = (const float*)d_in[4];
    const float* bo = (const float*)d_in[5];
    float* out = (float*)d_out;

    const int attn_smem = 4 * 64 * SROW * (int)sizeof(float);  // 69,632 B
    cudaFuncSetAttribute(attn_kernel, cudaFuncAttributeMaxDynamicSharedMemorySize,
                         attn_smem);

    dim3 blk(256);
    qkv_kernel<<<dim3(16, 128, 3), blk>>>(x, Wq, Wk, Wv);
    attn_kernel<<<dim3(32, 64), blk, attn_smem>>>();
    proj_kernel<<<dim3(16, 128), blk>>>(Wo, bo, out);
}

// round 3
// speedup vs baseline: 2.3788x; 2.3788x over previous
#include <cuda_runtime.h>
#include <cuda_bf16.h>
#include <math.h>
#include <stdint.h>

#define TSEQ 2048
#define CDIM 1024
#define HHEADS 16
#define DHEAD 64
#define KD 1024

typedef __nv_bfloat16 bf16;

// ---------------- scratch (static device arrays; allocation-free) -----------
#define NX ((size_t)8192 * 1024)
#define NW ((size_t)1024 * 1024)
#define NQ ((size_t)64 * 2048 * 64)
__device__ bf16 g_xhi[NX], g_xlo[NX];
__device__ bf16 g_whi[4 * NW], g_wlo[4 * NW];          // Wq,Wk,Wv,Wo stacked
__device__ bf16 g_qhi[NQ], g_qlo[NQ];                  // [bh][t][d], pre-scaled x8
__device__ bf16 g_khi[NQ], g_klo[NQ];                  // [bh][t][d]
__device__ bf16 g_vhi[NQ], g_vlo[NQ];                  // [bh][t][d]
__device__ bf16 g_ahi[NX], g_alo[NX];                  // attn out [b*T+t][h*64+d]

// ---------------- small helpers --------------------------------------------
__device__ __forceinline__ uint32_t smem_u32(const void* p) {
    uint32_t a;
    asm("{ .reg .u64 t; cvta.to.shared.u64 t, %1; cvt.u32.u64 %0, t; }"
        : "=r"(a) : "l"(p));
    return a;
}
__device__ __forceinline__ void cpasync16(uint32_t dst, const void* src) {
    asm volatile("cp.async.cg.shared.global [%0], [%1], 16;"
                 :: "r"(dst), "l"(src) : "memory");
}
#define CP_COMMIT() asm volatile("cp.async.commit_group;" ::: "memory")
#define CP_WAIT(N)  asm volatile("cp.async.wait_group %0;" :: "n"(N) : "memory")

__device__ __forceinline__ void ldm_x4(uint32_t* r, uint32_t a) {
    asm volatile("ldmatrix.sync.aligned.m8n8.x4.shared.b16 {%0,%1,%2,%3}, [%4];"
                 : "=r"(r[0]), "=r"(r[1]), "=r"(r[2]), "=r"(r[3]) : "r"(a));
}
__device__ __forceinline__ void ldm_x4t(uint32_t* r, uint32_t a) {
    asm volatile("ldmatrix.sync.aligned.m8n8.x4.trans.shared.b16 {%0,%1,%2,%3}, [%4];"
                 : "=r"(r[0]), "=r"(r[1]), "=r"(r[2]), "=r"(r[3]) : "r"(a));
}
__device__ __forceinline__ void mma_bf16(float* c, const uint32_t* a, const uint32_t* b) {
    asm volatile("mma.sync.aligned.m16n8k16.row.col.f32.bf16.bf16.f32 "
                 "{%0,%1,%2,%3}, {%4,%5,%6,%7}, {%8,%9}, {%0,%1,%2,%3};"
                 : "+f"(c[0]), "+f"(c[1]), "+f"(c[2]), "+f"(c[3])
                 : "r"(a[0]), "r"(a[1]), "r"(a[2]), "r"(a[3]), "r"(b[0]), "r"(b[1]));
}

__device__ __forceinline__ float bhi_f(float x) {
    return __bfloat162float(__float2bfloat16_rn(x));
}
__device__ __forceinline__ uint32_t pack2(float a, float b) {
    __nv_bfloat162 t;
    t.x = __float2bfloat16_rn(a);
    t.y = __float2bfloat16_rn(b);
    return *(uint32_t*)&t;
}

// ---------------- split kernel: fp32 -> (hi, lo) bf16 -----------------------
__global__ __launch_bounds__(256) void split_k(
    const float* __restrict__ s, bf16* __restrict__ hi, bf16* __restrict__ lo, int n4)
{
    int i = blockIdx.x * 256 + threadIdx.x;
    if (i >= n4) return;
    float4 v = ((const float4*)s)[i];
    float hx = bhi_f(v.x), hy = bhi_f(v.y), hz = bhi_f(v.z), hw = bhi_f(v.w);
    ((uint32_t*)hi)[2 * i]     = pack2(hx, hy);
    ((uint32_t*)hi)[2 * i + 1] = pack2(hz, hw);
    ((uint32_t*)lo)[2 * i]     = pack2(v.x - hx, v.y - hy);
    ((uint32_t*)lo)[2 * i + 1] = pack2(v.z - hz, v.w - hw);
}

// ---------------- GEMM: D[m][n] = sum_k A[m][k]*B[n][k]  (bf16x3) -----------
// 128x128 CTA tile, BK=32, 4-stage cp.async, 256 thr (8 warps = 2m x 4n).
// MODE 0: qkv (A = x split, B = W[z]; epilogue -> g_q/g_k/g_v split)
// MODE 1: proj (A = attn split, B = W[3]=Wo; epilogue adds bias -> out fp32)
#define GST 40960   // bytes per stage: 4 tiles of 128x(32+8 pad) bf16 (10240 each)

template <int MODE>
__global__ __launch_bounds__(256, 1) void gemm_bf3(
    const bf16* __restrict__ Ahi, const bf16* __restrict__ Alo,
    const float* __restrict__ bo, float* __restrict__ outp)
{
    extern __shared__ __align__(16) char smem[];
    const uint32_t sb = smem_u32(smem);

    const int tid = threadIdx.x, wid = tid >> 5, lid = tid & 31;
    const int wm = wid & 1, wn = wid >> 1;
    const int m0 = blockIdx.y * 128, n0 = blockIdx.x * 128;
    const int z = (MODE == 0) ? blockIdx.z : 3;

    const bf16* __restrict__ Bhi = g_whi + (size_t)z * NW;
    const bf16* __restrict__ Blo = g_wlo + (size_t)z * NW;

    float acc[4][4][4];
    #pragma unroll
    for (int a = 0; a < 4; a++)
        #pragma unroll
        for (int b = 0; b < 4; b++)
            #pragma unroll
            for (int cc2 = 0; cc2 < 4; cc2++) acc[a][b][cc2] = 0.f;

    auto load_stage = [&](int c) {
        const uint32_t st = sb + (uint32_t)(c & 3) * GST;
        const int k0 = c * 32;
        #pragma unroll
        for (int i = 0; i < 2; i++) {
            int p = tid + i * 256;            // 512 chunks of 16B per tile
            int row = p >> 2, cc = p & 3;
            uint32_t so = (uint32_t)(row * 80 + cc * 16);
            const char* ga = (const char*)(Ahi + (size_t)(m0 + row) * KD + k0) + cc * 16;
            const char* gb = (const char*)(Bhi + (size_t)(n0 + row) * KD + k0) + cc * 16;
            cpasync16(st + so, ga);
            cpasync16(st + 10240u + so,
                      (const char*)(Alo + (size_t)(m0 + row) * KD + k0) + cc * 16);
            cpasync16(st + 20480u + so, gb);
            cpasync16(st + 30720u + so,
                      (const char*)(Blo + (size_t)(n0 + row) * KD + k0) + cc * 16);
        }
        CP_COMMIT();
    };

    load_stage(0); load_stage(1); load_stage(2);

    for (int c = 0; c < 32; c++) {
        if (c <= 28) { CP_WAIT(2); } else if (c <= 30) { CP_WAIT(1); } else { CP_WAIT(0); }
        __syncthreads();
        if (c + 3 < 32) load_stage(c + 3);

        const uint32_t st = sb + (uint32_t)(c & 3) * GST;
        #pragma unroll
        for (int ks = 0; ks < 2; ks++) {
            const uint32_t krow = (uint32_t)((ks * 16 + (lid >> 4) * 8) * 2);
            uint32_t ah[4][4], al[4][4];
            #pragma unroll
            for (int mt = 0; mt < 4; mt++) {
                uint32_t ra = st + (uint32_t)((wm * 64 + mt * 16 + (lid & 15)) * 80) + krow;
                ldm_x4(ah[mt], ra);
                ldm_x4(al[mt], ra + 10240u);
            }
            uint32_t bh_[4][2], bl_[4][2];
            #pragma unroll
            for (int np = 0; np < 2; np++) {
                uint32_t rb = st + 20480u
                            + (uint32_t)((wn * 32 + np * 16 + (lid & 15)) * 80) + krow;
                uint32_t r[4], r2[4];
                ldm_x4(r, rb);
                ldm_x4(r2, rb + 10240u);
                bh_[2 * np][0] = r[0];  bh_[2 * np][1] = r[2];
                bh_[2 * np + 1][0] = r[1]; bh_[2 * np + 1][1] = r[3];
                bl_[2 * np][0] = r2[0]; bl_[2 * np][1] = r2[2];
                bl_[2 * np + 1][0] = r2[1]; bl_[2 * np + 1][1] = r2[3];
            }
            #pragma unroll
            for (int mt = 0; mt < 4; mt++)
                #pragma unroll
                for (int nt = 0; nt < 4; nt++) {
                    mma_bf16(acc[mt][nt], ah[mt], bh_[nt]);
                    mma_bf16(acc[mt][nt], ah[mt], bl_[nt]);
                    mma_bf16(acc[mt][nt], al[mt], bh_[nt]);
                }
        }
    }

    // epilogue
    #pragma unroll
    for (int mt = 0; mt < 4; mt++)
        #pragma unroll
        for (int nt = 0; nt < 4; nt++) {
            const float* cv = acc[mt][nt];
            const int mA = m0 + wm * 64 + mt * 16 + (lid >> 2);
            const int n  = n0 + wn * 32 + nt * 8 + 2 * (lid & 3);
            #pragma unroll
            for (int h2 = 0; h2 < 2; h2++) {
                const int m = mA + 8 * h2;
                float v0 = cv[2 * h2], v1 = cv[2 * h2 + 1];
                if (MODE == 1) {
                    *(float2*)(outp + (size_t)m * CDIM + n) =
                        make_float2(v0 + bo[n], v1 + bo[n + 1]);
                } else {
                    const float s = (z == 0) ? 8.f : 1.f;   // sqrt(HS) bug folded into Q
                    v0 *= s; v1 *= s;
                    const int b = m >> 11, t = m & 2047, hh = n >> 6, d = n & 63;
                    const size_t off = ((((size_t)b * HHEADS + hh) * TSEQ + t) * DHEAD + d);
                    bf16* dh = (z == 0) ? g_qhi : (z == 1) ? g_khi : g_vhi;
                    bf16* dl = (z == 0) ? g_qlo : (z == 1) ? g_klo : g_vlo;
                    float h0 = bhi_f(v0), h1 = bhi_f(v1);
                    ((uint32_t*)dh)[off >> 1] = pack2(h0, h1);
                    ((uint32_t*)dl)[off >> 1] = pack2(v0 - h0, v1 - h1);
                }
            }
        }
}

// ---------------- flash attention (bf16x3 mma) ------------------------------
// Per CTA: 128 q rows x one (b,h).  Key tiles of 64, double-buffered.
// smem: Qhi/Qlo [128][72], 2 KV stages {Khi,Klo,Vhi,Vlo}[64][72], Phi/Plo [128][72]
#define AQH 0u
#define AQL 18432u
#define AKV(s) (36864u + (uint32_t)(s) * 36864u)
#define APH 110592u
#define APL 129024u
#define ASMEM 147456

__global__ __launch_bounds__(256, 1) void attn_bf3()
{
    extern __shared__ __align__(16) char smem[];
    const uint32_t sb = smem_u32(smem);

    const int tid = threadIdx.x, wid = tid >> 5, lid = tid & 31;
    const int qt = 15 - blockIdx.x;       // heavy tiles first
    const int bh = blockIdx.y;
    const int q0 = qt * 128;
    const int wq0 = wid * 16;
    const int nkt = 2 * qt + 2;

    const bf16* Qh = g_qhi + (size_t)bh * TSEQ * DHEAD;
    const bf16* Ql = g_qlo + (size_t)bh * TSEQ * DHEAD;
    const bf16* Kh = g_khi + (size_t)bh * TSEQ * DHEAD;
    const bf16* Kl = g_klo + (size_t)bh * TSEQ * DHEAD;
    const bf16* Vh = g_vhi + (size_t)bh * TSEQ * DHEAD;
    const bf16* Vl = g_vlo + (size_t)bh * TSEQ * DHEAD;

    // Q tile: 128 rows x 64 bf16 (128B) = 1024 chunks per half
    #pragma unroll
    for (int i = 0; i < 4; i++) {
        int p = tid + i * 256;
        int row = p >> 3, cc = p & 7;
        uint32_t so = (uint32_t)(row * 144 + cc * 16);
        cpasync16(sb + AQH + so, (const char*)(Qh + (size_t)(q0 + row) * DHEAD) + cc * 16);
        cpasync16(sb + AQL + so, (const char*)(Ql + (size_t)(q0 + row) * DHEAD) + cc * 16);
    }
    auto load_kv = [&](int kt, int s) {
        const int kb = kt * 64;
        const uint32_t st = sb + AKV(s);
        #pragma unroll
        for (int i = 0; i < 2; i++) {
            int p = tid + i * 256;            // 512 chunks per array
            int row = p >> 3, cc = p & 7;
            uint32_t so = (uint32_t)(row * 144 + cc * 16);
            const size_t g = (size_t)(kb + row) * DHEAD;
            cpasync16(st + so,           (const char*)(Kh + g) + cc * 16);
            cpasync16(st + 9216u + so,   (const char*)(Kl + g) + cc * 16);
            cpasync16(st + 18432u + so,  (const char*)(Vh + g) + cc * 16);
            cpasync16(st + 27648u + so,  (const char*)(Vl + g) + cc * 16);
        }
    };
    load_kv(0, 0);
    CP_COMMIT();

    // wait Q + kv0, then load Q fragments once
    CP_WAIT(0);
    __syncthreads();
    uint32_t qh[4][4], ql[4][4];
    #pragma unroll
    for (int ks = 0; ks < 4; ks++) {
        uint32_t ra = sb + AQH + (uint32_t)((wq0 + (lid & 15)) * 144)
                    + (uint32_t)((ks * 16 + (lid >> 4) * 8) * 2);
        ldm_x4(qh[ks], ra);
        ldm_x4(ql[ks], ra + (AQL - AQH));
    }

    float oacc[8][4];
    #pragma unroll
    for (int a = 0; a < 8; a++)
        #pragma unroll
        for (int b = 0; b < 4; b++) oacc[a][b] = 0.f;
    float mA = -1e30f, mB = -1e30f, lA = 0.f, lB = 0.f;

    const int rowA = q0 + wq0 + (lid >> 2);
    const int rowB = rowA + 8;

    for (int kt = 0; kt < nkt; kt++) {
        CP_WAIT(0);
        __syncthreads();
        if (kt + 1 < nkt) { load_kv(kt + 1, (kt + 1) & 1); CP_COMMIT(); }

        const uint32_t st = sb + AKV(kt & 1);
        const int kb = kt * 64;

        // ---- S = Q.K^T ----
        float s[8][4];
        #pragma unroll
        for (int a = 0; a < 8; a++)
            #pragma unroll
            for (int b = 0; b < 4; b++) s[a][b] = 0.f;

        #pragma unroll
        for (int ks = 0; ks < 4; ks++) {
            const uint32_t krow = (uint32_t)((ks * 16 + (lid >> 4) * 8) * 2);
            uint32_t kh_[8][2], kl_[8][2];
            #pragma unroll
            for (int np = 0; np < 4; np++) {
                uint32_t rb = st + (uint32_t)((np * 16 + (lid & 15)) * 144) + krow;
                uint32_t r[4], r2[4];
                ldm_x4(r, rb);
                ldm_x4(r2, rb + 9216u);
                kh_[2 * np][0] = r[0];  kh_[2 * np][1] = r[2];
                kh_[2 * np + 1][0] = r[1]; kh_[2 * np + 1][1] = r[3];
                kl_[2 * np][0] = r2[0]; kl_[2 * np][1] = r2[2];
                kl_[2 * np + 1][0] = r2[1]; kl_[2 * np + 1][1] = r2[3];
            }
            #pragma unroll
            for (int nt = 0; nt < 8; nt++) {
                mma_bf16(s[nt], qh[ks], kh_[nt]);
                mma_bf16(s[nt], qh[ks], kl_[nt]);
                mma_bf16(s[nt], ql[ks], kh_[nt]);
            }
        }

        // ---- causal mask (only top-two key tiles can cross the diagonal) ----
        if (kt >= 2 * qt) {
            #pragma unroll
            for (int nt = 0; nt < 8; nt++) {
                const int c0 = kb + nt * 8 + 2 * (lid & 3);
                if (c0 > rowA)     s[nt][0] = -1e30f;
                if (c0 + 1 > rowA) s[nt][1] = -1e30f;
                if (c0 > rowB)     s[nt][2] = -1e30f;
                if (c0 + 1 > rowB) s[nt][3] = -1e30f;
            }
        }

        // ---- online softmax (two rows per thread, quad reduction) ----
        float mxA = -1e30f, mxB = -1e30f;
        #pragma unroll
        for (int nt = 0; nt < 8; nt++) {
            mxA = fmaxf(mxA, fmaxf(s[nt][0], s[nt][1]));
            mxB = fmaxf(mxB, fmaxf(s[nt][2], s[nt][3]));
        }
        #pragma unroll
        for (int o = 1; o <= 2; o <<= 1) {
            mxA = fmaxf(mxA, __shfl_xor_sync(0xffffffffu, mxA, o));
            mxB = fmaxf(mxB, __shfl_xor_sync(0xffffffffu, mxB, o));
        }
        const float mnA = fmaxf(mA, mxA), mnB = fmaxf(mB, mxB);
        const float aAl = __expf(mA - mnA), aBl = __expf(mB - mnB);
        float sumA = 0.f, sumB = 0.f;
        #pragma unroll
        for (int nt = 0; nt < 8; nt++) {
            s[nt][0] = __expf(s[nt][0] - mnA);
            s[nt][1] = __expf(s[nt][1] - mnA);
            s[nt][2] = __expf(s[nt][2] - mnB);
            s[nt][3] = __expf(s[nt][3] - mnB);
            sumA += s[nt][0] + s[nt][1];
            sumB += s[nt][2] + s[nt][3];
        }
        #pragma unroll
        for (int o = 1; o <= 2; o <<= 1) {
            sumA += __shfl_xor_sync(0xffffffffu, sumA, o);
            sumB += __shfl_xor_sync(0xffffffffu, sumB, o);
        }
        lA = lA * aAl + sumA;  lB = lB * aBl + sumB;
        mA = mnA;              mB = mnB;
        #pragma unroll
        for (int nt = 0; nt < 8; nt++) {
            oacc[nt][0] *= aAl; oacc[nt][1] *= aAl;
            oacc[nt][2] *= aBl; oacc[nt][3] *= aBl;
        }

        // ---- store split P to smem ----
        {
            const int rA = wq0 + (lid >> 2);
            const int colb = 2 * (lid & 3);
            #pragma unroll
            for (int nt = 0; nt < 8; nt++) {
                float h0 = bhi_f(s[nt][0]), h1 = bhi_f(s[nt][1]);
                float h2 = bhi_f(s[nt][2]), h3 = bhi_f(s[nt][3]);
                uint32_t oA = (uint32_t)(rA * 144 + (nt * 8 + colb) * 2);
                uint32_t oB = oA + 8u * 144u;
                *(uint32_t*)(smem + APH + oA) = pack2(h0, h1);
                *(uint32_t*)(smem + APL + oA) = pack2(s[nt][0] - h0, s[nt][1] - h1);
                *(uint32_t*)(smem + APH + oB) = pack2(h2, h3);
                *(uint32_t*)(smem + APL + oB) = pack2(s[nt][2] - h2, s[nt][3] - h3);
            }
        }
        __syncthreads();

        // ---- O += P.V  (A = P from smem, B = V via ldmatrix.trans) ----
        #pragma unroll
        for (int ks = 0; ks < 4; ks++) {
            uint32_t ph[4], pl[4];
            uint32_t pa = sb + APH + (uint32_t)((wq0 + (lid & 15)) * 144)
                        + (uint32_t)((ks * 16 + (lid >> 4) * 8) * 2);
            ldm_x4(ph, pa);
            ldm_x4(pl, pa + (APL - APH));

            uint32_t vh_[8][2], vl_[8][2];
            const uint32_t vrow = (uint32_t)((ks * 16 + (lid & 7) + ((lid >> 3) & 1) * 8) * 144);
            #pragma unroll
            for (int np = 0; np < 4; np++) {
                uint32_t rb = st + 18432u + vrow
                            + (uint32_t)((np * 16 + (lid >> 4) * 8) * 2);
                uint32_t r[4], r2[4];
                ldm_x4t(r, rb);
                ldm_x4t(r2, rb + 9216u);
                vh_[2 * np][0] = r[0];  vh_[2 * np][1] = r[1];
                vh_[2 * np + 1][0] = r[2]; vh_[2 * np + 1][1] = r[3];
                vl_[2 * np][0] = r2[0]; vl_[2 * np][1] = r2[1];
                vl_[2 * np + 1][0] = r2[2]; vl_[2 * np + 1][1] = r2[3];
            }
            #pragma unroll
            for (int nt = 0; nt < 8; nt++) {
                mma_bf16(oacc[nt], ph, vh_[nt]);
                mma_bf16(oacc[nt], ph, vl_[nt]);
                mma_bf16(oacc[nt], pl, vh_[nt]);
            }
        }
        __syncthreads();
    }

    // ---- epilogue: normalize, split, write g_a ----
    const float iA = 1.f / lA, iB = 1.f / lB;
    const int b = bh >> 4, h = bh & 15;
    #pragma unroll
    for (int nt = 0; nt < 8; nt++) {
        const int col = h * DHEAD + nt * 8 + 2 * (lid & 3);
        float v0 = oacc[nt][0] * iA, v1 = oacc[nt][1] * iA;
        float v2 = oacc[nt][2] * iB, v3 = oacc[nt][3] * iB;
        size_t oA = ((size_t)b * TSEQ + rowA) * CDIM + col;
        size_t oB = ((size_t)b * TSEQ + rowB) * CDIM + col;
        float h0 = bhi_f(v0), h1 = bhi_f(v1), h2 = bhi_f(v2), h3 = bhi_f(v3);
        ((uint32_t*)g_ahi)[oA >> 1] = pack2(h0, h1);
        ((uint32_t*)g_alo)[oA >> 1] = pack2(v0 - h0, v1 - h1);
        ((uint32_t*)g_ahi)[oB >> 1] = pack2(h2, h3);
        ((uint32_t*)g_alo)[oB >> 1] = pack2(v2 - h2, v3 - h3);
    }
}

// ---------------------------------------------------------------------------
extern "C" void kernel_launch(void* const* d_in, const int* in_sizes, int n_in,
                              void* d_out, int out_size)
{
    const float* x  = (const float*)d_in[0];
    const float* Wq = (const float*)d_in[1];
    const float* Wk = (const float*)d_in[2];
    const float* Wv = (const float*)d_in[3];
    const float* Wo = (const float*)d_in[4];
    const float* bo = (const float*)d_in[5];
    float* out = (float*)d_out;

    bf16 *xhi, *xlo, *whi, *wlo;
    cudaGetSymbolAddress((void**)&xhi, g_xhi);
    cudaGetSymbolAddress((void**)&xlo, g_xlo);
    cudaGetSymbolAddress((void**)&whi, g_whi);
    cudaGetSymbolAddress((void**)&wlo, g_wlo);

    // splits
    split_k<<<8192, 256>>>(x, xhi, xlo, (int)(NX / 4));
    split_k<<<1024, 256>>>(Wq, whi + 0 * NW, wlo + 0 * NW, (int)(NW / 4));
    split_k<<<1024, 256>>>(Wk, whi + 1 * NW, wlo + 1 * NW, (int)(NW / 4));
    split_k<<<1024, 256>>>(Wv, whi + 2 * NW, wlo + 2 * NW, (int)(NW / 4));
    split_k<<<1024, 256>>>(Wo, whi + 3 * NW, wlo + 3 * NW, (int)(NW / 4));

    const int gsm = 4 * GST;      // 163840
    cudaFuncSetAttribute(gemm_bf3<0>, cudaFuncAttributeMaxDynamicSharedMemorySize, gsm);
    cudaFuncSetAttribute(gemm_bf3<1>, cudaFuncAttributeMaxDynamicSharedMemorySize, gsm);
    cudaFuncSetAttribute(attn_bf3, cudaFuncAttributeMaxDynamicSharedMemorySize, ASMEM);

    bf16 *ahi, *alo;
    cudaGetSymbolAddress((void**)&ahi, g_ahi);
    cudaGetSymbolAddress((void**)&alo, g_alo);

    gemm_bf3<0><<<dim3(8, 64, 3), 256, gsm>>>(xhi, xlo, nullptr, nullptr);
    attn_bf3<<<dim3(16, 64), 256, ASMEM>>>();
    gemm_bf3<1><<<dim3(8, 64, 1), 256, gsm>>>(ahi, alo, bo, out);
}

// round 4
// speedup vs baseline: 2.3800x; 1.0005x over previous
#include <cuda_runtime.h>
#include <cuda_bf16.h>
#include <math.h>
#include <stdint.h>

#define TSEQ 2048
#define CDIM 1024
#define HHEADS 16
#define DHEAD 64
#define KD 1024

typedef __nv_bfloat16 bf16;

// ---------------- scratch (static device arrays; allocation-free) -----------
#define NX ((size_t)8192 * 1024)
#define NW ((size_t)1024 * 1024)
#define NQ ((size_t)64 * 2048 * 64)
__device__ bf16 g_xhi[NX], g_xlo[NX];
__device__ bf16 g_whi[4 * NW], g_wlo[4 * NW];          // Wq,Wk,Wv,Wo stacked
__device__ bf16 g_qhi[NQ], g_qlo[NQ];                  // [bh][t][d], pre-scaled x8
__device__ bf16 g_khi[NQ], g_klo[NQ];                  // [bh][t][d]
__device__ bf16 g_vhi[NQ], g_vlo[NQ];                  // [bh][t][d]
__device__ bf16 g_ahi[NX], g_alo[NX];                  // attn out [b*T+t][h*64+d]

// ---------------- small helpers --------------------------------------------
__device__ __forceinline__ uint32_t smem_u32(const void* p) {
    uint32_t a;
    asm("{ .reg .u64 t; cvta.to.shared.u64 t, %1; cvt.u32.u64 %0, t; }"
        : "=r"(a) : "l"(p));
    return a;
}
__device__ __forceinline__ void cpasync16(uint32_t dst, const void* src) {
    asm volatile("cp.async.cg.shared.global [%0], [%1], 16;"
                 :: "r"(dst), "l"(src) : "memory");
}
#define CP_COMMIT() asm volatile("cp.async.commit_group;" ::: "memory")
#define CP_WAIT(N)  asm volatile("cp.async.wait_group %0;" :: "n"(N) : "memory")

__device__ __forceinline__ void ldm_x4(uint32_t* r, uint32_t a) {
    asm volatile("ldmatrix.sync.aligned.m8n8.x4.shared.b16 {%0,%1,%2,%3}, [%4];"
                 : "=r"(r[0]), "=r"(r[1]), "=r"(r[2]), "=r"(r[3]) : "r"(a));
}
__device__ __forceinline__ void ldm_x4t(uint32_t* r, uint32_t a) {
    asm volatile("ldmatrix.sync.aligned.m8n8.x4.trans.shared.b16 {%0,%1,%2,%3}, [%4];"
                 : "=r"(r[0]), "=r"(r[1]), "=r"(r[2]), "=r"(r[3]) : "r"(a));
}
__device__ __forceinline__ void mma_bf16(float* c, const uint32_t* a, const uint32_t* b) {
    asm volatile("mma.sync.aligned.m16n8k16.row.col.f32.bf16.bf16.f32 "
                 "{%0,%1,%2,%3}, {%4,%5,%6,%7}, {%8,%9}, {%0,%1,%2,%3};"
                 : "+f"(c[0]), "+f"(c[1]), "+f"(c[2]), "+f"(c[3])
                 : "r"(a[0]), "r"(a[1]), "r"(a[2]), "r"(a[3]), "r"(b[0]), "r"(b[1]));
}

__device__ __forceinline__ float bhi_f(float x) {
    return __bfloat162float(__float2bfloat16_rn(x));
}
__device__ __forceinline__ uint32_t pack2(float a, float b) {
    __nv_bfloat162 t;
    t.x = __float2bfloat16_rn(a);
    t.y = __float2bfloat16_rn(b);
    return *(uint32_t*)&t;
}

// ---------------- split kernel: fp32 -> (hi, lo) bf16 -----------------------
__global__ __launch_bounds__(256) void split_k(
    const float* __restrict__ s, bf16* __restrict__ hi, bf16* __restrict__ lo, int n4)
{
    int i = blockIdx.x * 256 + threadIdx.x;
    if (i >= n4) return;
    float4 v = ((const float4*)s)[i];
    float hx = bhi_f(v.x), hy = bhi_f(v.y), hz = bhi_f(v.z), hw = bhi_f(v.w);
    ((uint32_t*)hi)[2 * i]     = pack2(hx, hy);
    ((uint32_t*)hi)[2 * i + 1] = pack2(hz, hw);
    ((uint32_t*)lo)[2 * i]     = pack2(v.x - hx, v.y - hy);
    ((uint32_t*)lo)[2 * i + 1] = pack2(v.z - hz, v.w - hw);
}

// ---------------- GEMM: D[m][n] = sum_k A[m][k]*B[n][k]  (bf16x3) -----------
// 128x128 CTA tile, BK=32, 4-stage cp.async, 256 thr (8 warps = 2m x 4n).
// MODE 0: qkv (A = x split, B = W[z]; epilogue -> g_q/g_k/g_v split)
// MODE 1: proj (A = attn split, B = W[3]=Wo; epilogue adds bias -> out fp32)
#define GST 40960   // bytes per stage: 4 tiles of 128x(32+8 pad) bf16 (10240 each)

template <int MODE>
__global__ __launch_bounds__(256, 1) void gemm_bf3(
    const bf16* __restrict__ Ahi, const bf16* __restrict__ Alo,
    const float* __restrict__ bo, float* __restrict__ outp)
{
    extern __shared__ __align__(16) char smem[];
    const uint32_t sb = smem_u32(smem);

    const int tid = threadIdx.x, wid = tid >> 5, lid = tid & 31;
    const int wm = wid & 1, wn = wid >> 1;
    const int m0 = blockIdx.y * 128, n0 = blockIdx.x * 128;
    const int z = (MODE == 0) ? blockIdx.z : 3;

    const bf16* __restrict__ Bhi = g_whi + (size_t)z * NW;
    const bf16* __restrict__ Blo = g_wlo + (size_t)z * NW;

    float acc[4][4][4];
    #pragma unroll
    for (int a = 0; a < 4; a++)
        #pragma unroll
        for (int b = 0; b < 4; b++)
            #pragma unroll
            for (int cc2 = 0; cc2 < 4; cc2++) acc[a][b][cc2] = 0.f;

    auto load_stage = [&](int c) {
        const uint32_t st = sb + (uint32_t)(c & 3) * GST;
        const int k0 = c * 32;
        #pragma unroll
        for (int i = 0; i < 2; i++) {
            int p = tid + i * 256;            // 512 chunks of 16B per tile
            int row = p >> 2, cc = p & 3;
            uint32_t so = (uint32_t)(row * 80 + cc * 16);
            const char* ga = (const char*)(Ahi + (size_t)(m0 + row) * KD + k0) + cc * 16;
            const char* gb = (const char*)(Bhi + (size_t)(n0 + row) * KD + k0) + cc * 16;
            cpasync16(st + so, ga);
            cpasync16(st + 10240u + so,
                      (const char*)(Alo + (size_t)(m0 + row) * KD + k0) + cc * 16);
            cpasync16(st + 20480u + so, gb);
            cpasync16(st + 30720u + so,
                      (const char*)(Blo + (size_t)(n0 + row) * KD + k0) + cc * 16);
        }
        CP_COMMIT();
    };

    load_stage(0); load_stage(1); load_stage(2);

    for (int c = 0; c < 32; c++) {
        if (c <= 28) { CP_WAIT(2); } else if (c <= 30) { CP_WAIT(1); } else { CP_WAIT(0); }
        __syncthreads();
        if (c + 3 < 32) load_stage(c + 3);

        const uint32_t st = sb + (uint32_t)(c & 3) * GST;
        #pragma unroll
        for (int ks = 0; ks < 2; ks++) {
            const uint32_t krow = (uint32_t)((ks * 16 + (lid >> 4) * 8) * 2);
            uint32_t ah[4][4], al[4][4];
            #pragma unroll
            for (int mt = 0; mt < 4; mt++) {
                uint32_t ra = st + (uint32_t)((wm * 64 + mt * 16 + (lid & 15)) * 80) + krow;
                ldm_x4(ah[mt], ra);
                ldm_x4(al[mt], ra + 10240u);
            }
            uint32_t bh_[4][2], bl_[4][2];
            #pragma unroll
            for (int np = 0; np < 2; np++) {
                uint32_t rb = st + 20480u
                            + (uint32_t)((wn * 32 + np * 16 + (lid & 15)) * 80) + krow;
                uint32_t r[4], r2[4];
                ldm_x4(r, rb);
                ldm_x4(r2, rb + 10240u);
                bh_[2 * np][0] = r[0];  bh_[2 * np][1] = r[2];
                bh_[2 * np + 1][0] = r[1]; bh_[2 * np + 1][1] = r[3];
                bl_[2 * np][0] = r2[0]; bl_[2 * np][1] = r2[2];
                bl_[2 * np + 1][0] = r2[1]; bl_[2 * np + 1][1] = r2[3];
            }
            #pragma unroll
            for (int mt = 0; mt < 4; mt++)
                #pragma unroll
                for (int nt = 0; nt < 4; nt++) {
                    mma_bf16(acc[mt][nt], ah[mt], bh_[nt]);
                    mma_bf16(acc[mt][nt], ah[mt], bl_[nt]);
                    mma_bf16(acc[mt][nt], al[mt], bh_[nt]);
                }
        }
    }

    // epilogue
    #pragma unroll
    for (int mt = 0; mt < 4; mt++)
        #pragma unroll
        for (int nt = 0; nt < 4; nt++) {
            const float* cv = acc[mt][nt];
            const int mA = m0 + wm * 64 + mt * 16 + (lid >> 2);
            const int n  = n0 + wn * 32 + nt * 8 + 2 * (lid & 3);
            #pragma unroll
            for (int h2 = 0; h2 < 2; h2++) {
                const int m = mA + 8 * h2;
                float v0 = cv[2 * h2], v1 = cv[2 * h2 + 1];
                if (MODE == 1) {
                    *(float2*)(outp + (size_t)m * CDIM + n) =
                        make_float2(v0 + bo[n], v1 + bo[n + 1]);
                } else {
                    const float s = (z == 0) ? 8.f : 1.f;   // sqrt(HS) bug folded into Q
                    v0 *= s; v1 *= s;
                    const int b = m >> 11, t = m & 2047, hh = n >> 6, d = n & 63;
                    const size_t off = ((((size_t)b * HHEADS + hh) * TSEQ + t) * DHEAD + d);
                    bf16* dh = (z == 0) ? g_qhi : (z == 1) ? g_khi : g_vhi;
                    bf16* dl = (z == 0) ? g_qlo : (z == 1) ? g_klo : g_vlo;
                    float h0 = bhi_f(v0), h1 = bhi_f(v1);
                    ((uint32_t*)dh)[off >> 1] = pack2(h0, h1);
                    ((uint32_t*)dl)[off >> 1] = pack2(v0 - h0, v1 - h1);
                }
            }
        }
}

// ---------------- flash attention (bf16x3 mma) ------------------------------
// Per CTA: 128 q rows x one (b,h).  Key tiles of 64, double-buffered.
// smem: Qhi/Qlo [128][72], 2 KV stages {Khi,Klo,Vhi,Vlo}[64][72], Phi/Plo [128][72]
#define AQH 0u
#define AQL 18432u
#define AKV(s) (36864u + (uint32_t)(s) * 36864u)
#define APH 110592u
#define APL 129024u
#define ASMEM 147456

__global__ __launch_bounds__(256, 1) void attn_bf3()
{
    extern __shared__ __align__(16) char smem[];
    const uint32_t sb = smem_u32(smem);

    const int tid = threadIdx.x, wid = tid >> 5, lid = tid & 31;
    const int qt = 15 - blockIdx.x;       // heavy tiles first
    const int bh = blockIdx.y;
    const int q0 = qt * 128;
    const int wq0 = wid * 16;
    const int nkt = 2 * qt + 2;

    const bf16* Qh = g_qhi + (size_t)bh * TSEQ * DHEAD;
    const bf16* Ql = g_qlo + (size_t)bh * TSEQ * DHEAD;
    const bf16* Kh = g_khi + (size_t)bh * TSEQ * DHEAD;
    const bf16* Kl = g_klo + (size_t)bh * TSEQ * DHEAD;
    const bf16* Vh = g_vhi + (size_t)bh * TSEQ * DHEAD;
    const bf16* Vl = g_vlo + (size_t)bh * TSEQ * DHEAD;

    // Q tile: 128 rows x 64 bf16 (128B) = 1024 chunks per half
    #pragma unroll
    for (int i = 0; i < 4; i++) {
        int p = tid + i * 256;
        int row = p >> 3, cc = p & 7;
        uint32_t so = (uint32_t)(row * 144 + cc * 16);
        cpasync16(sb + AQH + so, (const char*)(Qh + (size_t)(q0 + row) * DHEAD) + cc * 16);
        cpasync16(sb + AQL + so, (const char*)(Ql + (size_t)(q0 + row) * DHEAD) + cc * 16);
    }
    auto load_kv = [&](int kt, int s) {
        const int kb = kt * 64;
        const uint32_t st = sb + AKV(s);
        #pragma unroll
        for (int i = 0; i < 2; i++) {
            int p = tid + i * 256;            // 512 chunks per array
            int row = p >> 3, cc = p & 7;
            uint32_t so = (uint32_t)(row * 144 + cc * 16);
            const size_t g = (size_t)(kb + row) * DHEAD;
            cpasync16(st + so,           (const char*)(Kh + g) + cc * 16);
            cpasync16(st + 9216u + so,   (const char*)(Kl + g) + cc * 16);
            cpasync16(st + 18432u + so,  (const char*)(Vh + g) + cc * 16);
            cpasync16(st + 27648u + so,  (const char*)(Vl + g) + cc * 16);
        }
    };
    load_kv(0, 0);
    CP_COMMIT();

    // wait Q + kv0, then load Q fragments once
    CP_WAIT(0);
    __syncthreads();
    uint32_t qh[4][4], ql[4][4];
    #pragma unroll
    for (int ks = 0; ks < 4; ks++) {
        uint32_t ra = sb + AQH + (uint32_t)((wq0 + (lid & 15)) * 144)
                    + (uint32_t)((ks * 16 + (lid >> 4) * 8) * 2);
        ldm_x4(qh[ks], ra);
        ldm_x4(ql[ks], ra + (AQL - AQH));
    }

    float oacc[8][4];
    #pragma unroll
    for (int a = 0; a < 8; a++)
        #pragma unroll
        for (int b = 0; b < 4; b++) oacc[a][b] = 0.f;
    float mA = -1e30f, mB = -1e30f, lA = 0.f, lB = 0.f;

    const int rowA = q0 + wq0 + (lid >> 2);
    const int rowB = rowA + 8;

    for (int kt = 0; kt < nkt; kt++) {
        CP_WAIT(0);
        __syncthreads();
        if (kt + 1 < nkt) { load_kv(kt + 1, (kt + 1) & 1); CP_COMMIT(); }

        const uint32_t st = sb + AKV(kt & 1);
        const int kb = kt * 64;

        // ---- S = Q.K^T ----
        float s[8][4];
        #pragma unroll
        for (int a = 0; a < 8; a++)
            #pragma unroll
            for (int b = 0; b < 4; b++) s[a][b] = 0.f;

        #pragma unroll
        for (int ks = 0; ks < 4; ks++) {
            const uint32_t krow = (uint32_t)((ks * 16 + (lid >> 4) * 8) * 2);
            uint32_t kh_[8][2], kl_[8][2];
            #pragma unroll
            for (int np = 0; np < 4; np++) {
                uint32_t rb = st + (uint32_t)((np * 16 + (lid & 15)) * 144) + krow;
                uint32_t r[4], r2[4];
                ldm_x4(r, rb);
                ldm_x4(r2, rb + 9216u);
                kh_[2 * np][0] = r[0];  kh_[2 * np][1] = r[2];
                kh_[2 * np + 1][0] = r[1]; kh_[2 * np + 1][1] = r[3];
                kl_[2 * np][0] = r2[0]; kl_[2 * np][1] = r2[2];
                kl_[2 * np + 1][0] = r2[1]; kl_[2 * np + 1][1] = r2[3];
            }
            #pragma unroll
            for (int nt = 0; nt < 8; nt++) {
                mma_bf16(s[nt], qh[ks], kh_[nt]);
                mma_bf16(s[nt], qh[ks], kl_[nt]);
                mma_bf16(s[nt], ql[ks], kh_[nt]);
            }
        }

        // ---- causal mask (only top-two key tiles can cross the diagonal) ----
        if (kt >= 2 * qt) {
            #pragma unroll
            for (int nt = 0; nt < 8; nt++) {
                const int c0 = kb + nt * 8 + 2 * (lid & 3);
                if (c0 > rowA)     s[nt][0] = -1e30f;
                if (c0 + 1 > rowA) s[nt][1] = -1e30f;
                if (c0 > rowB)     s[nt][2] = -1e30f;
                if (c0 + 1 > rowB) s[nt][3] = -1e30f;
            }
        }

        // ---- online softmax (two rows per thread, quad reduction) ----
        float mxA = -1e30f, mxB = -1e30f;
        #pragma unroll
        for (int nt = 0; nt < 8; nt++) {
            mxA = fmaxf(mxA, fmaxf(s[nt][0], s[nt][1]));
            mxB = fmaxf(mxB, fmaxf(s[nt][2], s[nt][3]));
        }
        #pragma unroll
        for (int o = 1; o <= 2; o <<= 1) {
            mxA = fmaxf(mxA, __shfl_xor_sync(0xffffffffu, mxA, o));
            mxB = fmaxf(mxB, __shfl_xor_sync(0xffffffffu, mxB, o));
        }
        const float mnA = fmaxf(mA, mxA), mnB = fmaxf(mB, mxB);
        const float aAl = __expf(mA - mnA), aBl = __expf(mB - mnB);
        float sumA = 0.f, sumB = 0.f;
        #pragma unroll
        for (int nt = 0; nt < 8; nt++) {
            s[nt][0] = __expf(s[nt][0] - mnA);
            s[nt][1] = __expf(s[nt][1] - mnA);
            s[nt][2] = __expf(s[nt][2] - mnB);
            s[nt][3] = __expf(s[nt][3] - mnB);
            sumA += s[nt][0] + s[nt][1];
            sumB += s[nt][2] + s[nt][3];
        }
        #pragma unroll
        for (int o = 1; o <= 2; o <<= 1) {
            sumA += __shfl_xor_sync(0xffffffffu, sumA, o);
            sumB += __shfl_xor_sync(0xffffffffu, sumB, o);
        }
        lA = lA * aAl + sumA;  lB = lB * aBl + sumB;
        mA = mnA;              mB = mnB;
        #pragma unroll
        for (int nt = 0; nt < 8; nt++) {
            oacc[nt][0] *= aAl; oacc[nt][1] *= aAl;
            oacc[nt][2] *= aBl; oacc[nt][3] *= aBl;
        }

        // ---- store split P to smem ----
        {
            const int rA = wq0 + (lid >> 2);
            const int colb = 2 * (lid & 3);
            #pragma unroll
            for (int nt = 0; nt < 8; nt++) {
                float h0 = bhi_f(s[nt][0]), h1 = bhi_f(s[nt][1]);
                float h2 = bhi_f(s[nt][2]), h3 = bhi_f(s[nt][3]);
                uint32_t oA = (uint32_t)(rA * 144 + (nt * 8 + colb) * 2);
                uint32_t oB = oA + 8u * 144u;
                *(uint32_t*)(smem + APH + oA) = pack2(h0, h1);
                *(uint32_t*)(smem + APL + oA) = pack2(s[nt][0] - h0, s[nt][1] - h1);
                *(uint32_t*)(smem + APH + oB) = pack2(h2, h3);
                *(uint32_t*)(smem + APL + oB) = pack2(s[nt][2] - h2, s[nt][3] - h3);
            }
        }
        __syncthreads();

        // ---- O += P.V  (A = P from smem, B = V via ldmatrix.trans) ----
        #pragma unroll
        for (int ks = 0; ks < 4; ks++) {
            uint32_t ph[4], pl[4];
            uint32_t pa = sb + APH + (uint32_t)((wq0 + (lid & 15)) * 144)
                        + (uint32_t)((ks * 16 + (lid >> 4) * 8) * 2);
            ldm_x4(ph, pa);
            ldm_x4(pl, pa + (APL - APH));

            uint32_t vh_[8][2], vl_[8][2];
            const uint32_t vrow = (uint32_t)((ks * 16 + (lid & 7) + ((lid >> 3) & 1) * 8) * 144);
            #pragma unroll
            for (int np = 0; np < 4; np++) {
                uint32_t rb = st + 18432u + vrow
                            + (uint32_t)((np * 16 + (lid >> 4) * 8) * 2);
                uint32_t r[4], r2[4];
                ldm_x4t(r, rb);
                ldm_x4t(r2, rb + 9216u);
                vh_[2 * np][0] = r[0];  vh_[2 * np][1] = r[1];
                vh_[2 * np + 1][0] = r[2]; vh_[2 * np + 1][1] = r[3];
                vl_[2 * np][0] = r2[0]; vl_[2 * np][1] = r2[1];
                vl_[2 * np + 1][0] = r2[2]; vl_[2 * np + 1][1] = r2[3];
            }
            #pragma unroll
            for (int nt = 0; nt < 8; nt++) {
                mma_bf16(oacc[nt], ph, vh_[nt]);
                mma_bf16(oacc[nt], ph, vl_[nt]);
                mma_bf16(oacc[nt], pl, vh_[nt]);
            }
        }
        __syncthreads();
    }

    // ---- epilogue: normalize, split, write g_a ----
    const float iA = 1.f / lA, iB = 1.f / lB;
    const int b = bh >> 4, h = bh & 15;
    #pragma unroll
    for (int nt = 0; nt < 8; nt++) {
        const int col = h * DHEAD + nt * 8 + 2 * (lid & 3);
        float v0 = oacc[nt][0] * iA, v1 = oacc[nt][1] * iA;
        float v2 = oacc[nt][2] * iB, v3 = oacc[nt][3] * iB;
        size_t oA = ((size_t)b * TSEQ + rowA) * CDIM + col;
        size_t oB = ((size_t)b * TSEQ + rowB) * CDIM + col;
        float h0 = bhi_f(v0), h1 = bhi_f(v1), h2 = bhi_f(v2), h3 = bhi_f(v3);
        ((uint32_t*)g_ahi)[oA >> 1] = pack2(h0, h1);
        ((uint32_t*)g_alo)[oA >> 1] = pack2(v0 - h0, v1 - h1);
        ((uint32_t*)g_ahi)[oB >> 1] = pack2(h2, h3);
        ((uint32_t*)g_alo)[oB >> 1] = pack2(v2 - h2, v3 - h3);
    }
}

// ---------------------------------------------------------------------------
extern "C" void kernel_launch(void* const* d_in, const int* in_sizes, int n_in,
                              void* d_out, int out_size)
{
    const float* x  = (const float*)d_in[0];
    const float* Wq = (const float*)d_in[1];
    const float* Wk = (const float*)d_in[2];
    const float* Wv = (const float*)d_in[3];
    const float* Wo = (const float*)d_in[4];
    const float* bo = (const float*)d_in[5];
    float* out = (float*)d_out;

    bf16 *xhi, *xlo, *whi, *wlo;
    cudaGetSymbolAddress((void**)&xhi, g_xhi);
    cudaGetSymbolAddress((void**)&xlo, g_xlo);
    cudaGetSymbolAddress((void**)&whi, g_whi);
    cudaGetSymbolAddress((void**)&wlo, g_wlo);

    // splits
    split_k<<<8192, 256>>>(x, xhi, xlo, (int)(NX / 4));
    split_k<<<1024, 256>>>(Wq, whi + 0 * NW, wlo + 0 * NW, (int)(NW / 4));
    split_k<<<1024, 256>>>(Wk, whi + 1 * NW, wlo + 1 * NW, (int)(NW / 4));
    split_k<<<1024, 256>>>(Wv, whi + 2 * NW, wlo + 2 * NW, (int)(NW / 4));
    split_k<<<1024, 256>>>(Wo, whi + 3 * NW, wlo + 3 * NW, (int)(NW / 4));

    const int gsm = 4 * GST;      // 163840
    cudaFuncSetAttribute(gemm_bf3<0>, cudaFuncAttributeMaxDynamicSharedMemorySize, gsm);
    cudaFuncSetAttribute(gemm_bf3<1>, cudaFuncAttributeMaxDynamicSharedMemorySize, gsm);
    cudaFuncSetAttribute(attn_bf3, cudaFuncAttributeMaxDynamicSharedMemorySize, ASMEM);

    bf16 *ahi, *alo;
    cudaGetSymbolAddress((void**)&ahi, g_ahi);
    cudaGetSymbolAddress((void**)&alo, g_alo);

    gemm_bf3<0><<<dim3(8, 64, 3), 256, gsm>>>(xhi, xlo, nullptr, nullptr);
    attn_bf3<<<dim3(16, 64), 256, ASMEM>>>();
    gemm_bf3<1><<<dim3(8, 64, 1), 256, gsm>>>(ahi, alo, bo, out);
}